// round 12
// baseline (speedup 1.0000x reference)
#include <cuda_runtime.h>
#include <math.h>
#include <mma.h>
using namespace nvcuda;

#define B_    1024
#define V_    64
#define L1_   6
#define D_    512
#define NROWS 1152   // V * 3 * 6 distinct (var, cat, lag) combos
#define NEMB  73     // 64 var + 3 strength + 6 lag partial-GEMM rows
#define KCH   8      // k-split chunks for the embedding GEMM
#define KSP   4      // k-split for the table GEMM

// Static scratch (no allocations allowed)
__device__ float g_rowsP[KCH * NEMB * D_];  // k-split partials of emb @ W1
__device__ float g_Tpre_hi[NROWS * D_];     // relu rows, tf32 hi part
__device__ float g_Tpre_lo[NROWS * D_];     // relu rows, tf32 lo part
__device__ float g_W2h[D_ * D_];            // W2 tf32 hi
__device__ float g_W2l[D_ * D_];            // W2 tf32 lo
__device__ float g_Tp[KSP * NROWS * D_];    // table GEMM k-partials
__device__ float g_T[NROWS * D_];           // final row table
__device__ int   g_idx[B_ * V_];            // per (b,v) combo index

__device__ __forceinline__ float tf32r(float x) {
    unsigned int o;
    asm("cvt.rna.tf32.f32 %0, %1;" : "=r"(o) : "f"(x));
    return __uint_as_float(o);
}

// ---------------------------------------------------------------------------
// Kernel 0: W2 -> tf32 hi/lo split (3xTF32 prep)
// ---------------------------------------------------------------------------
__global__ __launch_bounds__(256) void w2prep_kernel(const float* __restrict__ W2) {
    const int i = (blockIdx.x * 256 + threadIdx.x) * 4;
    float4 x = *(const float4*)(W2 + i);
    float4 h, l;
    h.x = tf32r(x.x); l.x = tf32r(x.x - h.x);
    h.y = tf32r(x.y); l.y = tf32r(x.y - h.y);
    h.z = tf32r(x.z); l.z = tf32r(x.z - h.z);
    h.w = tf32r(x.w); l.w = tf32r(x.w - h.w);
    *(float4*)(g_W2h + i) = h;
    *(float4*)(g_W2l + i) = l;
}

// ---------------------------------------------------------------------------
// Kernel 1: per (b,v) strength category + dominant lag -> combo index.
// ---------------------------------------------------------------------------
__global__ __launch_bounds__(96) void reduce_kernel(const float* __restrict__ cm) {
    __shared__ float sh_s[V_ * L1_];
    __shared__ float sh_a[V_ * L1_];
    const int b = blockIdx.x;
    const int t = threadIdx.x;                  // 0..95
    const float4* p = (const float4*)(cm + (size_t)b * (V_ * V_ * L1_)) + t;
    float4 s = make_float4(0.f, 0.f, 0.f, 0.f);
    float4 a = make_float4(0.f, 0.f, 0.f, 0.f);
#pragma unroll 8
    for (int c = 0; c < V_; ++c) {
        float4 x = __ldcs(&p[c * 96]);          // streamed once: evict-first
        s.x += x.x; s.y += x.y; s.z += x.z; s.w += x.w;
        a.x += fabsf(x.x); a.y += fabsf(x.y); a.z += fabsf(x.z); a.w += fabsf(x.w);
    }
    sh_s[4 * t + 0] = s.x; sh_s[4 * t + 1] = s.y; sh_s[4 * t + 2] = s.z; sh_s[4 * t + 3] = s.w;
    sh_a[4 * t + 0] = a.x; sh_a[4 * t + 1] = a.y; sh_a[4 * t + 2] = a.z; sh_a[4 * t + 3] = a.w;
    __syncthreads();
    if (t < V_) {                               // t = v
        const int base = t * L1_;
        float tot  = sh_s[base];
        float best = sh_a[base];
        int   bl   = 0;
#pragma unroll
        for (int l = 1; l < L1_; ++l) {
            tot += sh_s[base + l];
            float av = sh_a[base + l];
            if (av > best) { best = av; bl = l; }    // first-max (jnp.argmax)
        }
        float mean = tot * (1.0f / (float)(V_ * L1_));
        int cat = (mean > 0.1f) ? 1 : ((mean < -0.1f) ? 2 : 0);
        g_idx[b * V_ + t] = t * 18 + cat * 6 + bl;
    }
}

// ---------------------------------------------------------------------------
// Kernel 2: embedding partial GEMM, k-split by KCH=8 (k chunks of 64).
// ---------------------------------------------------------------------------
__global__ __launch_bounds__(D_) void emb_gemm_kernel(
    const float* __restrict__ vt, const float* __restrict__ st,
    const float* __restrict__ lt, const float* __restrict__ W1) {
    const int g  = blockIdx.x;   // 0..18 row group
    const int kc = blockIdx.y;   // 0..KCH-1 k chunk
    const int d  = threadIdx.x;

    int r0g, nrows, koff;
    const float* src;
    if (g < 16)       { nrows = 4;                 koff = 0;      r0g = g * 4;          src = vt + g * 4 * D_; }
    else if (g == 16) { nrows = 3;                 koff = D_;     r0g = 64;             src = st; }
    else              { int o = (g - 17) * 4;
                        nrows = (6 - o < 4) ? (6 - o) : 4;
                        koff = 2 * D_;             r0g = 67 + o;  src = lt + o * D_; }

    __shared__ float se[4 * D_];
    for (int r = 0; r < nrows; ++r) se[r * D_ + d] = src[r * D_ + d];
    for (int r = nrows; r < 4; ++r) se[r * D_ + d] = 0.f;
    __syncthreads();

    const int k0 = kc * (D_ / KCH);
    float acc[4] = {0.f, 0.f, 0.f, 0.f};
    const float* w = W1 + (size_t)(koff + k0) * D_ + d;
#pragma unroll 8
    for (int k = 0; k < D_ / KCH; ++k) {
        float wv = w[(size_t)k * D_];
#pragma unroll
        for (int r = 0; r < 4; ++r) acc[r] = fmaf(se[r * D_ + k0 + k], wv, acc[r]);
    }
    for (int r = 0; r < nrows; ++r)
        g_rowsP[(size_t)(kc * NEMB + r0g + r) * D_ + d] = acc[r];
}

// ---------------------------------------------------------------------------
// Kernel 3: g_Tpre_{hi,lo}[r] = tf32split( relu( sum_kc partials + b1 ) )
// ---------------------------------------------------------------------------
__global__ __launch_bounds__(D_) void tpre_kernel(const float* __restrict__ b1) {
    const int r = blockIdx.x;
    const int d = threadIdx.x;
    const int v = r / 18, rem = r % 18, c = rem / 6, l = rem % 6;
    float x = b1[d];
#pragma unroll
    for (int kc = 0; kc < KCH; ++kc) {
        const float* base = g_rowsP + (size_t)kc * NEMB * D_;
        x += base[v * D_ + d] + base[(64 + c) * D_ + d] + base[(67 + l) * D_ + d];
    }
    x = fmaxf(x, 0.f);
    float hi = tf32r(x);
    g_Tpre_hi[r * D_ + d] = hi;
    g_Tpre_lo[r * D_ + d] = tf32r(x - hi);
}

// ---------------------------------------------------------------------------
// Kernel 4: 3xTF32 tensor-core table GEMM, k-split by 4.
// g_Tp[z] = Tpre(1152x512) @ W2[kz quarter] via wmma m16n16k8:
//   acc += Ahi*Bhi + Ahi*Blo + Alo*Bhi   (error ~1e-6, cuBLAS 3xTF32)
// BM=64, BN=64, BK=16, 128 threads (4 warps, 16 rows x 64 cols each),
// register-prefetch double buffer. grid (18, 8, 4) = 576 CTAs.
// ---------------------------------------------------------------------------
#define BM 64
#define BN 64
#define BK 16
#define NKB (D_ / (BK * KSP))   // 8 k-blocks per CTA
#define ALD 20                  // sA row stride (floats)
#define BLD 68                  // sB row stride (floats)
__global__ __launch_bounds__(128) void gemm_T_tf32() {
    __shared__ float sA[2][2][BM][ALD];  // [buf][hi/lo][m][k]
    __shared__ float sB[2][2][BK][BLD];  // [buf][hi/lo][k][n]
    const int bm  = blockIdx.x;   // 0..17
    const int bn  = blockIdx.y;   // 0..7
    const int kz  = blockIdx.z;   // 0..3
    const int tid = threadIdx.x;
    const int w   = tid >> 5;     // warp 0..3 -> rows w*16..w*16+15

    const int kbase = kz * (D_ / KSP);

    // A: thread t loads row a_m, k range [a_k, a_k+8) as 2 float4 (x hi/lo)
    const int a_m = tid >> 1;          // 0..63
    const int a_k = (tid & 1) * 8;     // 0 or 8
    // B: thread t loads k-row b_k, n range [b_n, b_n+8) as 2 float4 (x hi/lo)
    const int b_k = tid >> 3;          // 0..15
    const int b_n = (tid & 7) * 8;     // 0..56

    const float* Ah = g_Tpre_hi + (size_t)(bm * BM + a_m) * D_ + kbase + a_k;
    const float* Al = g_Tpre_lo + (size_t)(bm * BM + a_m) * D_ + kbase + a_k;
    const float* Bh = g_W2h + (size_t)(kbase + b_k) * D_ + bn * BN + b_n;
    const float* Bl = g_W2l + (size_t)(kbase + b_k) * D_ + bn * BN + b_n;

    wmma::fragment<wmma::accumulator, 16, 16, 8, float> acc[4];
#pragma unroll
    for (int f = 0; f < 4; ++f) wmma::fill_fragment(acc[f], 0.f);

    float4 pah0, pah1, pal0, pal1, pbh0, pbh1, pbl0, pbl1;

    // prologue: fetch k-block 0
    pah0 = *(const float4*)(Ah);     pah1 = *(const float4*)(Ah + 4);
    pal0 = *(const float4*)(Al);     pal1 = *(const float4*)(Al + 4);
    pbh0 = *(const float4*)(Bh);     pbh1 = *(const float4*)(Bh + 4);
    pbl0 = *(const float4*)(Bl);     pbl1 = *(const float4*)(Bl + 4);
    *(float4*)&sA[0][0][a_m][a_k]     = pah0;
    *(float4*)&sA[0][0][a_m][a_k + 4] = pah1;
    *(float4*)&sA[0][1][a_m][a_k]     = pal0;
    *(float4*)&sA[0][1][a_m][a_k + 4] = pal1;
    *(float4*)&sB[0][0][b_k][b_n]     = pbh0;
    *(float4*)&sB[0][0][b_k][b_n + 4] = pbh1;
    *(float4*)&sB[0][1][b_k][b_n]     = pbl0;
    *(float4*)&sB[0][1][b_k][b_n + 4] = pbl1;
    __syncthreads();

#pragma unroll 1
    for (int kb = 0; kb < NKB; ++kb) {
        const int cur = kb & 1;
        if (kb + 1 < NKB) {
            const int k0 = (kb + 1) * BK;
            pah0 = *(const float4*)(Ah + k0);     pah1 = *(const float4*)(Ah + k0 + 4);
            pal0 = *(const float4*)(Al + k0);     pal1 = *(const float4*)(Al + k0 + 4);
            pbh0 = *(const float4*)(Bh + (size_t)k0 * D_);
            pbh1 = *(const float4*)(Bh + (size_t)k0 * D_ + 4);
            pbl0 = *(const float4*)(Bl + (size_t)k0 * D_);
            pbl1 = *(const float4*)(Bl + (size_t)k0 * D_ + 4);
        }
#pragma unroll
        for (int ks = 0; ks < 2; ++ks) {
            wmma::fragment<wmma::matrix_a, 16, 16, 8, wmma::precision::tf32, wmma::row_major> a_h, a_l;
            wmma::load_matrix_sync(a_h, &sA[cur][0][w * 16][ks * 8], ALD);
            wmma::load_matrix_sync(a_l, &sA[cur][1][w * 16][ks * 8], ALD);
#pragma unroll
            for (int f = 0; f < 4; ++f) {
                wmma::fragment<wmma::matrix_b, 16, 16, 8, wmma::precision::tf32, wmma::row_major> b_h, b_l;
                wmma::load_matrix_sync(b_h, &sB[cur][0][ks * 8][f * 16], BLD);
                wmma::load_matrix_sync(b_l, &sB[cur][1][ks * 8][f * 16], BLD);
                wmma::mma_sync(acc[f], a_h, b_h, acc[f]);
                wmma::mma_sync(acc[f], a_h, b_l, acc[f]);
                wmma::mma_sync(acc[f], a_l, b_h, acc[f]);
            }
        }
        if (kb + 1 < NKB) {
            const int nxt = cur ^ 1;
            *(float4*)&sA[nxt][0][a_m][a_k]     = pah0;
            *(float4*)&sA[nxt][0][a_m][a_k + 4] = pah1;
            *(float4*)&sA[nxt][1][a_m][a_k]     = pal0;
            *(float4*)&sA[nxt][1][a_m][a_k + 4] = pal1;
            *(float4*)&sB[nxt][0][b_k][b_n]     = pbh0;
            *(float4*)&sB[nxt][0][b_k][b_n + 4] = pbh1;
            *(float4*)&sB[nxt][1][b_k][b_n]     = pbl0;
            *(float4*)&sB[nxt][1][b_k][b_n + 4] = pbl1;
            __syncthreads();
        }
    }

    float* Tout = g_Tp + (size_t)kz * NROWS * D_;
    const int m0 = bm * BM + w * 16;
#pragma unroll
    for (int f = 0; f < 4; ++f)
        wmma::store_matrix_sync(&Tout[(size_t)m0 * D_ + bn * BN + f * 16],
                                acc[f], D_, wmma::mem_row_major);
}

// ---------------------------------------------------------------------------
// Kernel 4b: g_T = sum_z g_Tp[z] + b2  (L2-resident)
// ---------------------------------------------------------------------------
__global__ __launch_bounds__(256) void combine_kernel(const float* __restrict__ b2) {
    const int i = blockIdx.x * 256 + threadIdx.x;     // float4 index
    const int d4 = i & 127;                           // float4 within row
    float4 bb = *(const float4*)(b2 + d4 * 4);
    float4 o = bb;
#pragma unroll
    for (int z = 0; z < KSP; ++z) {
        float4 p = *(const float4*)&g_Tp[((size_t)z * NROWS * (D_ / 4) + i) * 4];
        o.x += p.x; o.y += p.y; o.z += p.z; o.w += p.w;
    }
    *(float4*)&g_T[(size_t)i * 4] = o;
}

// ---------------------------------------------------------------------------
// Kernel 5: out[row] = g_T[idx[row]] — v-major block order, evict-first writes
// ---------------------------------------------------------------------------
__global__ __launch_bounds__(512) void gather_kernel(float* __restrict__ out) {
    const int v    = blockIdx.x >> 8;                   // 0..63
    const int bg   = blockIdx.x & 255;                  // 0..255
    const int b    = bg * 4 + (threadIdx.x >> 7);       // batch index
    const int lane = threadIdx.x & 127;                 // 128 float4 = 512 floats
    const int row  = b * V_ + v;
    const int r    = g_idx[row];
    const float4* src = (const float4*)(g_T + (size_t)r * D_);
    float4* dst = (float4*)(out + (size_t)row * D_);
    __stcs(&dst[lane], src[lane]);
}

// ---------------------------------------------------------------------------
extern "C" void kernel_launch(void* const* d_in, const int* in_sizes, int n_in,
                              void* d_out, int out_size) {
    const float* cm = (const float*)d_in[0];
    const float* vt = (const float*)d_in[1];
    const float* st = (const float*)d_in[2];
    const float* lt = (const float*)d_in[3];
    const float* W1 = (const float*)d_in[4];
    const float* b1 = (const float*)d_in[5];
    const float* W2 = (const float*)d_in[6];
    const float* b2 = (const float*)d_in[7];
    float* out = (float*)d_out;

    static cudaStream_t s2 = nullptr;
    static cudaEvent_t  evFork = nullptr, evReduce = nullptr;
    if (!s2) {
        cudaStreamCreateWithFlags(&s2, cudaStreamNonBlocking);
        cudaEventCreateWithFlags(&evFork,   cudaEventDisableTiming);
        cudaEventCreateWithFlags(&evReduce, cudaEventDisableTiming);
    }

    // Fork: reduce (independent) on s2, table chain on main stream.
    cudaEventRecord(evFork, 0);
    cudaStreamWaitEvent(s2, evFork, 0);
    reduce_kernel<<<B_, 96, 0, s2>>>(cm);
    cudaEventRecord(evReduce, s2);

    w2prep_kernel<<<(D_ * D_ / 4) / 256, 256>>>(W2);
    dim3 ge(19, KCH);
    emb_gemm_kernel<<<ge, D_>>>(vt, st, lt, W1);
    tpre_kernel<<<NROWS, D_>>>(b1);
    dim3 gg(NROWS / BM, D_ / BN, KSP);
    gemm_T_tf32<<<gg, 128>>>();
    combine_kernel<<<(NROWS * D_ / 4) / 256, 256>>>(b2);

    // Join: gather needs both the table (main stream) and idx (s2).
    cudaStreamWaitEvent(0, evReduce, 0);
    gather_kernel<<<(B_ * V_) / 4, 512>>>(out);
}

// round 13
// speedup vs baseline: 1.3453x; 1.3453x over previous
#include <cuda_runtime.h>
#include <math.h>

#define B_    1024
#define V_    64
#define L1_   6
#define D_    512
#define NROWS 1152   // V * 3 * 6 distinct (var, cat, lag) combos
#define NEMB  73     // 64 var + 3 strength + 6 lag partial-GEMM rows
#define KCH   8      // k-split chunks for the embedding GEMM
#define KSP   4      // k-split for the table GEMM

// Static scratch (no allocations allowed)
__device__ float g_rowsP[KCH * NEMB * D_];  // k-split partials of emb @ W1
__device__ float g_Tpre[NROWS * D_];        // relu(...) rows
__device__ float g_Tp[KSP * NROWS * D_];    // table GEMM k-partials
__device__ float g_T[NROWS * D_];           // final row table
__device__ int   g_idx[B_ * V_];            // per (b,v) combo index

// ---------------------------------------------------------------------------
// Kernel 1: per (b,v) strength category + dominant lag -> combo index.
// (round-6 proven version: 96 threads, c-ascending per-slot accumulation)
// ---------------------------------------------------------------------------
__global__ __launch_bounds__(96) void reduce_kernel(const float* __restrict__ cm) {
    __shared__ float sh_s[V_ * L1_];
    __shared__ float sh_a[V_ * L1_];
    const int b = blockIdx.x;
    const int t = threadIdx.x;                  // 0..95
    const float4* p = (const float4*)(cm + (size_t)b * (V_ * V_ * L1_)) + t;
    float4 s = make_float4(0.f, 0.f, 0.f, 0.f);
    float4 a = make_float4(0.f, 0.f, 0.f, 0.f);
#pragma unroll 8
    for (int c = 0; c < V_; ++c) {
        float4 x = __ldcs(&p[c * 96]);          // streamed once: evict-first
        s.x += x.x; s.y += x.y; s.z += x.z; s.w += x.w;
        a.x += fabsf(x.x); a.y += fabsf(x.y); a.z += fabsf(x.z); a.w += fabsf(x.w);
    }
    sh_s[4 * t + 0] = s.x; sh_s[4 * t + 1] = s.y; sh_s[4 * t + 2] = s.z; sh_s[4 * t + 3] = s.w;
    sh_a[4 * t + 0] = a.x; sh_a[4 * t + 1] = a.y; sh_a[4 * t + 2] = a.z; sh_a[4 * t + 3] = a.w;
    __syncthreads();
    if (t < V_) {                               // t = v
        const int base = t * L1_;
        float tot  = sh_s[base];
        float best = sh_a[base];
        int   bl   = 0;
#pragma unroll
        for (int l = 1; l < L1_; ++l) {
            tot += sh_s[base + l];
            float av = sh_a[base + l];
            if (av > best) { best = av; bl = l; }    // first-max (jnp.argmax)
        }
        float mean = tot * (1.0f / (float)(V_ * L1_));
        int cat = (mean > 0.1f) ? 1 : ((mean < -0.1f) ? 2 : 0);
        g_idx[b * V_ + t] = t * 18 + cat * 6 + bl;
    }
}

// ---------------------------------------------------------------------------
// Kernel 2: embedding partial GEMM, k-split by KCH=8 (k chunks of 64).
// ---------------------------------------------------------------------------
__global__ __launch_bounds__(D_) void emb_gemm_kernel(
    const float* __restrict__ vt, const float* __restrict__ st,
    const float* __restrict__ lt, const float* __restrict__ W1) {
    const int g  = blockIdx.x;   // 0..18 row group
    const int kc = blockIdx.y;   // 0..KCH-1 k chunk
    const int d  = threadIdx.x;

    int r0g, nrows, koff;
    const float* src;
    if (g < 16)       { nrows = 4;                 koff = 0;      r0g = g * 4;          src = vt + g * 4 * D_; }
    else if (g == 16) { nrows = 3;                 koff = D_;     r0g = 64;             src = st; }
    else              { int o = (g - 17) * 4;
                        nrows = (6 - o < 4) ? (6 - o) : 4;
                        koff = 2 * D_;             r0g = 67 + o;  src = lt + o * D_; }

    __shared__ float se[4 * D_];
    for (int r = 0; r < nrows; ++r) se[r * D_ + d] = src[r * D_ + d];
    for (int r = nrows; r < 4; ++r) se[r * D_ + d] = 0.f;
    __syncthreads();

    const int k0 = kc * (D_ / KCH);
    float acc[4] = {0.f, 0.f, 0.f, 0.f};
    const float* w = W1 + (size_t)(koff + k0) * D_ + d;
#pragma unroll 8
    for (int k = 0; k < D_ / KCH; ++k) {
        float wv = w[(size_t)k * D_];
#pragma unroll
        for (int r = 0; r < 4; ++r) acc[r] = fmaf(se[r * D_ + k0 + k], wv, acc[r]);
    }
    for (int r = 0; r < nrows; ++r)
        g_rowsP[(size_t)(kc * NEMB + r0g + r) * D_ + d] = acc[r];
}

// ---------------------------------------------------------------------------
// Kernel 3: g_Tpre[r] = relu( sum_kc partials + b1 )
// ---------------------------------------------------------------------------
__global__ __launch_bounds__(D_) void tpre_kernel(const float* __restrict__ b1) {
    const int r = blockIdx.x;
    const int d = threadIdx.x;
    const int v = r / 18, rem = r % 18, c = rem / 6, l = rem % 6;
    float x = b1[d];
#pragma unroll
    for (int kc = 0; kc < KCH; ++kc) {
        const float* base = g_rowsP + (size_t)kc * NEMB * D_;
        x += base[v * D_ + d] + base[(64 + c) * D_ + d] + base[(67 + l) * D_ + d];
    }
    g_Tpre[r * D_ + d] = fmaxf(x, 0.f);
}

// ---------------------------------------------------------------------------
// Kernel 4: g_Tp[z] = g_Tpre(1152x512) @ W2[kz quarter], k-split by 4.
// BM=64, BN=64, BK=16, 128 threads, 8x4 micro, reg-prefetch double buffer.
// grid (18, 8, 4) = 576 CTAs. (Round-6 proven config: 19.5 us.)
// ---------------------------------------------------------------------------
#define BM 64
#define BN 64
#define BK 16
#define NKB (D_ / (BK * KSP))   // 8 k-blocks per CTA
#define APAD 68
__global__ __launch_bounds__(128) void gemm_T_kernel(const float* __restrict__ W2) {
    __shared__ float As[2][BK][APAD];  // k-major A tile (padded)
    __shared__ float Bs[2][BK][BN];
    const int bm  = blockIdx.x;   // 0..17
    const int bn  = blockIdx.y;   // 0..7
    const int kz  = blockIdx.z;   // 0..3
    const int tid = threadIdx.x;
    const int tx  = tid & 15;     // n micro (4 cols)
    const int ty  = tid >> 4;     // m micro (8 rows)

    const int kbase = kz * (D_ / KSP);

    const int a_m = tid >> 2;          // 0..31 (and +32)
    const int a_k = (tid & 3) * 4;     // 0,4,8,12
    const int b_k = tid >> 4;          // 0..7
    const int b_n = (tid & 15) * 4;    // 0..60

    const float* Aptr = g_Tpre + (size_t)(bm * BM) * D_ + kbase;
    const float* Bptr = W2 + (size_t)kbase * D_ + bn * BN;

    float acc[8][4] = {};
    float4 pa0, pa1, pb0, pb1;

    pa0 = *(const float4*)(Aptr + (size_t)a_m        * D_ + a_k);
    pa1 = *(const float4*)(Aptr + (size_t)(a_m + 32) * D_ + a_k);
    pb0 = *(const float4*)(Bptr + (size_t)(b_k + 0) * D_ + b_n);
    pb1 = *(const float4*)(Bptr + (size_t)(b_k + 8) * D_ + b_n);
    {
        As[0][a_k + 0][a_m] = pa0.x; As[0][a_k + 1][a_m] = pa0.y;
        As[0][a_k + 2][a_m] = pa0.z; As[0][a_k + 3][a_m] = pa0.w;
        As[0][a_k + 0][a_m + 32] = pa1.x; As[0][a_k + 1][a_m + 32] = pa1.y;
        As[0][a_k + 2][a_m + 32] = pa1.z; As[0][a_k + 3][a_m + 32] = pa1.w;
        *(float4*)&Bs[0][b_k + 0][b_n] = pb0;
        *(float4*)&Bs[0][b_k + 8][b_n] = pb1;
    }
    __syncthreads();

#pragma unroll 1
    for (int kb = 0; kb < NKB; ++kb) {
        const int cur = kb & 1;
        if (kb + 1 < NKB) {
            const int k0 = (kb + 1) * BK;
            pa0 = *(const float4*)(Aptr + (size_t)a_m        * D_ + k0 + a_k);
            pa1 = *(const float4*)(Aptr + (size_t)(a_m + 32) * D_ + k0 + a_k);
            pb0 = *(const float4*)(Bptr + (size_t)(k0 + b_k + 0) * D_ + b_n);
            pb1 = *(const float4*)(Bptr + (size_t)(k0 + b_k + 8) * D_ + b_n);
        }
#pragma unroll
        for (int kk = 0; kk < BK; ++kk) {
            float4 a0 = *(const float4*)&As[cur][kk][ty * 8];
            float4 a1 = *(const float4*)&As[cur][kk][ty * 8 + 4];
            float4 bv = *(const float4*)&Bs[cur][kk][tx * 4];
            float arr[8] = {a0.x, a0.y, a0.z, a0.w, a1.x, a1.y, a1.z, a1.w};
            float brr[4] = {bv.x, bv.y, bv.z, bv.w};
#pragma unroll
            for (int i = 0; i < 8; ++i)
#pragma unroll
                for (int j = 0; j < 4; ++j)
                    acc[i][j] = fmaf(arr[i], brr[j], acc[i][j]);
        }
        if (kb + 1 < NKB) {
            const int nxt = cur ^ 1;
            As[nxt][a_k + 0][a_m] = pa0.x; As[nxt][a_k + 1][a_m] = pa0.y;
            As[nxt][a_k + 2][a_m] = pa0.z; As[nxt][a_k + 3][a_m] = pa0.w;
            As[nxt][a_k + 0][a_m + 32] = pa1.x; As[nxt][a_k + 1][a_m + 32] = pa1.y;
            As[nxt][a_k + 2][a_m + 32] = pa1.z; As[nxt][a_k + 3][a_m + 32] = pa1.w;
            *(float4*)&Bs[nxt][b_k + 0][b_n] = pb0;
            *(float4*)&Bs[nxt][b_k + 8][b_n] = pb1;
            __syncthreads();
        }
    }

    float* Tout = g_Tp + (size_t)kz * NROWS * D_;
    const int m0 = bm * BM + ty * 8;
    const int n0 = bn * BN + tx * 4;
#pragma unroll
    for (int i = 0; i < 8; ++i) {
        float4 o;
        o.x = acc[i][0]; o.y = acc[i][1]; o.z = acc[i][2]; o.w = acc[i][3];
        *(float4*)&Tout[(size_t)(m0 + i) * D_ + n0] = o;
    }
}

// ---------------------------------------------------------------------------
// Kernel 4b: g_T = sum_z g_Tp[z] + b2  (L2-resident)
// ---------------------------------------------------------------------------
__global__ __launch_bounds__(256) void combine_kernel(const float* __restrict__ b2) {
    const int i = blockIdx.x * 256 + threadIdx.x;     // float4 index
    const int d4 = i & 127;                           // float4 within row
    float4 bb = *(const float4*)(b2 + d4 * 4);
    float4 o = bb;
#pragma unroll
    for (int z = 0; z < KSP; ++z) {
        float4 p = *(const float4*)&g_Tp[((size_t)z * NROWS * (D_ / 4) + i) * 4];
        o.x += p.x; o.y += p.y; o.z += p.z; o.w += p.w;
    }
    *(float4*)&g_T[(size_t)i * 4] = o;
}

// ---------------------------------------------------------------------------
// Kernel 5 (v2): out[row] = g_T[idx[row]] with INTRA-BLOCK row reuse.
// Block = (v, 64-batch range): loops over its 64 output rows sequentially.
// All rows share v -> at most 18 distinct table rows (~36 KB) -> after first
// touch they're L1-resident, collapsing L2 read traffic 134 MB -> ~20 MB.
// Writes are evict-first (__stcs), 2 KB contiguous per row.
// grid 1024 blocks (~7/SM), 512 threads (4 rows x 128 float4 lanes per iter).
// ---------------------------------------------------------------------------
__global__ __launch_bounds__(512) void gather_kernel(float* __restrict__ out) {
    const int v    = blockIdx.x >> 4;                   // 0..63
    const int grp  = blockIdx.x & 15;                   // 0..15 (64 b's each)
    const int sub  = threadIdx.x >> 7;                  // 0..3
    const int lane = threadIdx.x & 127;                 // 128 float4 = 512 floats
#pragma unroll 4
    for (int it = 0; it < 16; ++it) {
        const int b   = grp * 64 + it * 4 + sub;
        const int row = b * V_ + v;
        const int r   = g_idx[row];                     // broadcast per 128 lanes
        const float4* src = (const float4*)(g_T + (size_t)r * D_);
        float4* dst = (float4*)(out + (size_t)row * D_);
        __stcs(&dst[lane], __ldg(&src[lane]));          // read L1-resident, write evict-first
    }
}

// ---------------------------------------------------------------------------
extern "C" void kernel_launch(void* const* d_in, const int* in_sizes, int n_in,
                              void* d_out, int out_size) {
    const float* cm = (const float*)d_in[0];
    const float* vt = (const float*)d_in[1];
    const float* st = (const float*)d_in[2];
    const float* lt = (const float*)d_in[3];
    const float* W1 = (const float*)d_in[4];
    const float* b1 = (const float*)d_in[5];
    const float* W2 = (const float*)d_in[6];
    const float* b2 = (const float*)d_in[7];
    float* out = (float*)d_out;

    static cudaStream_t s2 = nullptr;
    static cudaEvent_t  evFork = nullptr, evReduce = nullptr;
    if (!s2) {
        cudaStreamCreateWithFlags(&s2, cudaStreamNonBlocking);
        cudaEventCreateWithFlags(&evFork,   cudaEventDisableTiming);
        cudaEventCreateWithFlags(&evReduce, cudaEventDisableTiming);
    }

    // Fork: reduce (independent) on s2, table chain on main stream.
    cudaEventRecord(evFork, 0);
    cudaStreamWaitEvent(s2, evFork, 0);
    reduce_kernel<<<B_, 96, 0, s2>>>(cm);
    cudaEventRecord(evReduce, s2);

    dim3 ge(19, KCH);
    emb_gemm_kernel<<<ge, D_>>>(vt, st, lt, W1);
    tpre_kernel<<<NROWS, D_>>>(b1);
    dim3 gg(NROWS / BM, D_ / BN, KSP);
    gemm_T_kernel<<<gg, 128>>>(W2);
    combine_kernel<<<(NROWS * D_ / 4) / 256, 256>>>(b2);

    // Join: gather needs both the table (main stream) and idx (s2).
    cudaStreamWaitEvent(0, evReduce, 0);
    gather_kernel<<<V_ * 16, 512>>>(out);
}